// round 7
// baseline (speedup 1.0000x reference)
#include <cuda_runtime.h>

// EncodecQuantizer RVQ: x [B,T,D] f32, embed [NQ,K,D] f32 -> codes [NQ,B*T]
// written as float32 (harness output dtype confirmed in R3).
#define BB    16
#define TT    4096
#define DD    128
#define NQ    8
#define KK    1024
#define NTOK  (BB * TT)       // 65536
#define MTILE 64              // tokens per block
#define NTILE 64              // codes per smem tile
#define BLKT  256             // threads per block (16 x 16)
#define RSTR  68              // R smem row stride (floats)
#define BSTR  68              // B smem row stride (floats)
#define EPS   3.0e-3f         // fp32 near-tie window -> fp64 recheck

typedef unsigned long long u64;

// smem layout (floats): R[128][RSTR] | B[128][BSTR] | bestk[64] (as int)
#define SM_R_FLOATS (DD * RSTR)
#define SM_B_FLOATS (DD * BSTR)
#define SMEM_BYTES  ((SM_R_FLOATS + SM_B_FLOATS + MTILE) * 4)

__device__ float g_norms[NQ * KK];

__global__ void norms_kernel(const float* __restrict__ embed) {
    int k = blockIdx.x * blockDim.x + threadIdx.x;
    if (k >= NQ * KK) return;
    const float* e = embed + (size_t)k * DD;
    float s = 0.0f;
#pragma unroll
    for (int i = 0; i < DD; i++) s = fmaf(e[i], e[i], s);
    g_norms[k] = s;
}

// Packed f32x2 FMA (Blackwell): acc += a * b per 32-bit lane.
#define FMA2(acc, av, bv) \
    asm("fma.rn.f32x2 %0, %1, %2, %0;" : "+l"(acc) : "l"(av), "l"(bv))

__device__ __forceinline__ float lo32(u64 a) {
    return __uint_as_float((unsigned int)(a & 0xffffffffull));
}
__device__ __forceinline__ float hi32(u64 a) {
    return __uint_as_float((unsigned int)(a >> 32));
}
__device__ __forceinline__ u64 dup_lo(u64 v) {
    unsigned int b = (unsigned int)v;
    return (u64)b | ((u64)b << 32);
}
__device__ __forceinline__ u64 dup_hi(u64 v) {
    unsigned int b = (unsigned int)(v >> 32);
    return (u64)b | ((u64)b << 32);
}

// Exact (fp64) distance for token column of smem R vs codeword e (global).
__device__ double dist_exact_col(const float* __restrict__ R, int tok,
                                 const float* __restrict__ e) {
    double dot = 0.0, nrm = 0.0;
#pragma unroll 4
    for (int d = 0; d < DD; d++) {
        double r = (double)R[d * RSTR + tok];
        double v = (double)__ldg(e + d);
        dot += r * v;
        nrm += v * v;
    }
    return 2.0 * dot - nrm;
}

// ---------------------------------------------------------------------------
// Register-tiled RVQ: block owns 64 tokens (residual in smem, [d][tok]).
// Per stage: 16 code tiles of 64 (transposed into smem); each thread computes
// a 4-token x 4-code tile via packed-f32x2 rank-1 updates. Per-token top-2 is
// merged across 16 code lanes by shuffle; near-ties resolved exactly in fp64.
// Small tiles on purpose: 3 blocks/SM -> 6 warps/SMSP for latency hiding.
// ---------------------------------------------------------------------------
__global__ void __launch_bounds__(BLKT, 3)
rvq_kernel(const float* __restrict__ x,
           const float* __restrict__ embed,
           float* __restrict__ codes) {
    extern __shared__ float sm[];
    float* R  = sm;                          // [DD][RSTR]
    float* Bt = sm + SM_R_FLOATS;            // [DD][BSTR]
    int*   bk = (int*)(sm + SM_R_FLOATS + SM_B_FLOATS);  // [MTILE]

    const int tid = threadIdx.x;
    const int tx  = tid & 15;     // code-lane
    const int ty  = tid >> 4;     // token-lane (0..15), 4 tokens each
    const int tok0 = blockIdx.x * MTILE;

    // ---- Load x -> R transposed ([d][tok]); 4 threads per token ----
    {
        int tok = tid & 63, quarter = tid >> 6;   // quarter: 32 d-values
        const float4* xr = reinterpret_cast<const float4*>(
            x + (size_t)(tok0 + tok) * DD + quarter * 32);
#pragma unroll
        for (int j = 0; j < 8; j++) {
            float4 v = xr[j];
            int d = quarter * 32 + j * 4;
            R[(d + 0) * RSTR + tok] = v.x;
            R[(d + 1) * RSTR + tok] = v.y;
            R[(d + 2) * RSTR + tok] = v.z;
            R[(d + 3) * RSTR + tok] = v.w;
        }
    }
    __syncthreads();

    for (int s = 0; s < NQ; s++) {
        const float* es = embed + (size_t)s * KK * DD;

        // per-token top-2 (4 tokens per thread, over this thread's codes)
        float d1[4], d2v[4];
        int   k1[4], k2[4];
#pragma unroll
        for (int i = 0; i < 4; i++) {
            d1[i] = -3.402823466e+38f; d2v[i] = -3.402823466e+38f;
            k1[i] = 0; k2[i] = 0;
        }

        for (int t = 0; t < KK / NTILE; t++) {
            __syncthreads();   // previous tile's readers done
            // ---- Load code tile -> Bt transposed ([d][code]) ----
            {
                int code = tid >> 2;      // 0..63
                int dg0  = tid & 3;
                const float* eg = es + (size_t)(t * NTILE + code) * DD;
#pragma unroll
                for (int it = 0; it < 8; it++) {
                    int dg = dg0 + it * 4;            // 0..31
                    float4 v = *reinterpret_cast<const float4*>(eg + dg * 4);
                    int d = dg * 4;
                    Bt[(d + 0) * BSTR + code] = v.x;
                    Bt[(d + 1) * BSTR + code] = v.y;
                    Bt[(d + 2) * BSTR + code] = v.z;
                    Bt[(d + 3) * BSTR + code] = v.w;
                }
            }
            __syncthreads();

            // ---- 4x4 micro-GEMM over K=128 (token pairs packed) ----
            u64 acc[8];
#pragma unroll
            for (int i = 0; i < 8; i++) acc[i] = 0ull;

            const float* ra = R + ty * 4;
            const float* rb = Bt + tx * 4;
#pragma unroll 8
            for (int k = 0; k < DD; k++) {
                ulonglong2 av =
                    *reinterpret_cast<const ulonglong2*>(ra + k * RSTR);
                ulonglong2 bv =
                    *reinterpret_cast<const ulonglong2*>(rb + k * BSTR);
                u64 b0 = dup_lo(bv.x), b1 = dup_hi(bv.x);
                u64 b2 = dup_lo(bv.y), b3 = dup_hi(bv.y);
                FMA2(acc[0], av.x, b0); FMA2(acc[1], av.y, b0);
                FMA2(acc[2], av.x, b1); FMA2(acc[3], av.y, b1);
                FMA2(acc[4], av.x, b2); FMA2(acc[5], av.y, b2);
                FMA2(acc[6], av.x, b3); FMA2(acc[7], av.y, b3);
            }

            // ---- Epilogue: distances + top-2 (ascending code order) ----
            int kb0 = t * NTILE + tx * 4;
#pragma unroll
            for (int c = 0; c < 4; c++) {
                float nj = __ldg(&g_norms[s * KK + kb0 + c]);
                int kc = kb0 + c;
#pragma unroll
                for (int p = 0; p < 2; p++) {
                    u64 a = acc[c * 2 + p];
                    float dl = 2.0f * lo32(a) - nj;   // token 2p
                    float dh = 2.0f * hi32(a) - nj;   // token 2p+1
                    int il = 2 * p, ih = 2 * p + 1;
                    if (dl > d1[il]) {
                        d2v[il] = d1[il]; k2[il] = k1[il];
                        d1[il] = dl; k1[il] = kc;
                    } else if (dl > d2v[il]) { d2v[il] = dl; k2[il] = kc; }
                    if (dh > d1[ih]) {
                        d2v[ih] = d1[ih]; k2[ih] = k1[ih];
                        d1[ih] = dh; k1[ih] = kc;
                    } else if (dh > d2v[ih]) { d2v[ih] = dh; k2[ih] = kc; }
                }
            }
        }

        // ---- Merge top-2 across 16 code lanes (xor stays within tx group) ----
#pragma unroll
        for (int m = 1; m < 16; m <<= 1) {
#pragma unroll
            for (int i = 0; i < 4; i++) {
                float od1 = __shfl_xor_sync(0xffffffffu, d1[i], m);
                int   ok1 = __shfl_xor_sync(0xffffffffu, k1[i], m);
                float od2 = __shfl_xor_sync(0xffffffffu, d2v[i], m);
                int   ok2 = __shfl_xor_sync(0xffffffffu, k2[i], m);
                bool ob = (od1 > d1[i]) || (od1 == d1[i] && ok1 < k1[i]);
                if (ob) {
                    bool sb = (d1[i] > od2) || (d1[i] == od2 && k1[i] < ok2);
                    d2v[i] = sb ? d1[i] : od2;
                    k2[i]  = sb ? k1[i] : ok2;
                    d1[i] = od1; k1[i] = ok1;
                } else {
                    bool sb = (od1 > d2v[i]) || (od1 == d2v[i] && ok1 < k2[i]);
                    if (sb) { d2v[i] = od1; k2[i] = ok1; }
                }
            }
        }

        // ---- Finalize per token (tx==0), exact recheck on near-ties ----
        if (tx == 0) {
#pragma unroll 1
            for (int i = 0; i < 4; i++) {
                int tok = ty * 4 + i;
                int kbest = k1[i];
                if (d1[i] - d2v[i] <= EPS) {
                    double e1 = dist_exact_col(R, tok, es + (size_t)k1[i] * DD);
                    double e2 = dist_exact_col(R, tok, es + (size_t)k2[i] * DD);
                    if (e2 > e1 || (e2 == e1 && k2[i] < k1[i])) kbest = k2[i];
                }
                bk[tok] = kbest;
            }
        }
        __syncthreads();

        // ---- Emit codes + residual update (4 threads per token) ----
        {
            int tok = tid & 63, quarter = tid >> 6;
            int kb2 = bk[tok];
            if (quarter == 0)
                codes[(size_t)s * NTOK + tok0 + tok] = (float)kb2;
            const float4* eb = reinterpret_cast<const float4*>(
                es + (size_t)kb2 * DD + quarter * 32);
#pragma unroll
            for (int j = 0; j < 8; j++) {
                float4 v = eb[j];
                int d = quarter * 32 + j * 4;
                R[(d + 0) * RSTR + tok] -= v.x;
                R[(d + 1) * RSTR + tok] -= v.y;
                R[(d + 2) * RSTR + tok] -= v.z;
                R[(d + 3) * RSTR + tok] -= v.w;
            }
        }
        __syncthreads();
    }
}

extern "C" void kernel_launch(void* const* d_in, const int* in_sizes, int n_in,
                              void* d_out, int out_size) {
    const float* p0 = (const float*)d_in[0];
    const float* p1 = (const float*)d_in[1];
    const float* x;
    const float* embed;
    if (in_sizes[0] > in_sizes[1]) { x = p0; embed = p1; }
    else                           { x = p1; embed = p0; }
    float* codes = (float*)d_out;

    cudaFuncSetAttribute(rvq_kernel,
                         cudaFuncAttributeMaxDynamicSharedMemorySize,
                         SMEM_BYTES);

    norms_kernel<<<(NQ * KK + 255) / 256, 256>>>(embed);
    rvq_kernel<<<NTOK / MTILE, BLKT, SMEM_BYTES>>>(x, embed, codes);
}